// round 3
// baseline (speedup 1.0000x reference)
#include <cuda_runtime.h>

// 2-level 2D Haar DWT, fully fused, 4x8 input tile per thread.
// x: [96, 512, 512] fp32.
// out layout (tuple order):
//   a2,h2,v2,d2 : [96,128,128]  (L2ELEMS each)
//   h1,v1,d1    : [96,256,256]  (4*L2ELEMS each)

#define L2ELEMS (96u * 128u * 128u)   // 1,572,864

// 2x2 Haar butterfly: inputs (tl,tr,bl,br) -> (aa, h, v, d)
#define BFLY(tl, tr, bl, br, aa, hh, vv, dd)          \
    {                                                  \
        float _sT = (tl) + (tr), _sB = (bl) + (br);    \
        float _dT = (tl) - (tr), _dB = (bl) - (br);    \
        aa = 0.5f * (_sT + _sB);                       \
        hh = 0.5f * (_sT - _sB);                       \
        vv = 0.5f * (_dT + _dB);                       \
        dd = 0.5f * (_dT - _dB);                       \
    }

__global__ void __launch_bounds__(256) haar2_kernel(const float* __restrict__ x,
                                                    float* __restrict__ out)
{
    unsigned tid = blockIdx.x * blockDim.x + threadIdx.x;   // 0 .. 96*128*64-1
    unsigned w8 = tid & 63u;            // 8-wide block col (64 per row)
    unsigned h  = (tid >> 6) & 127u;    // 4-high block row
    unsigned bc = tid >> 13;            // batch*channel, 0..95

    const float4* xp = (const float4*)(x + ((size_t)bc * 512u + 4u * h) * 512u + 8u * w8);
    // 8 independent loads issued up front (MLP=8)
    float4 r0a = __ldcs(xp);
    float4 r0b = __ldcs(xp + 1);
    float4 r1a = __ldcs(xp + 128);
    float4 r1b = __ldcs(xp + 129);
    float4 r2a = __ldcs(xp + 256);
    float4 r2b = __ldcs(xp + 257);
    float4 r3a = __ldcs(xp + 384);
    float4 r3b = __ldcs(xp + 385);

    // ---- level-1: eight 2x2 butterflies ----
    // left 4x4 (cols 0-3)
    float aaL00, aaL01, aaL10, aaL11;
    float4 h1r0, h1r1, v1r0, v1r1, d1r0, d1r1;  // rows 2h and 2h+1, 4 cols each

    BFLY(r0a.x, r0a.y, r1a.x, r1a.y, aaL00, h1r0.x, v1r0.x, d1r0.x);
    BFLY(r0a.z, r0a.w, r1a.z, r1a.w, aaL01, h1r0.y, v1r0.y, d1r0.y);
    BFLY(r2a.x, r2a.y, r3a.x, r3a.y, aaL10, h1r1.x, v1r1.x, d1r1.x);
    BFLY(r2a.z, r2a.w, r3a.z, r3a.w, aaL11, h1r1.y, v1r1.y, d1r1.y);

    // right 4x4 (cols 4-7)
    float aaR00, aaR01, aaR10, aaR11;
    BFLY(r0b.x, r0b.y, r1b.x, r1b.y, aaR00, h1r0.z, v1r0.z, d1r0.z);
    BFLY(r0b.z, r0b.w, r1b.z, r1b.w, aaR01, h1r0.w, v1r0.w, d1r0.w);
    BFLY(r2b.x, r2b.y, r3b.x, r3b.y, aaR10, h1r1.z, v1r1.z, d1r1.z);
    BFLY(r2b.z, r2b.w, r3b.z, r3b.w, aaR11, h1r1.w, v1r1.w, d1r1.w);

    // ---- level-2: two butterflies on aa's ----
    float2 a2v, h2v, v2v, d2v;
    BFLY(aaL00, aaL01, aaL10, aaL11, a2v.x, h2v.x, v2v.x, d2v.x);
    BFLY(aaR00, aaR01, aaR10, aaR11, a2v.y, h2v.y, v2v.y, d2v.y);

    // ---- stores ----
    float* h1o = out + (size_t)4 * L2ELEMS;
    float* v1o = out + (size_t)8 * L2ELEMS;
    float* d1o = out + (size_t)12 * L2ELEMS;

    // level-1: [96,256,256], rows 2h/2h+1, cols 4*w8..4*w8+3 -> float4
    size_t base1 = (size_t)bc * 65536u + (size_t)(2u * h) * 256u + 4u * w8;
    __stcs((float4*)(h1o + base1),        h1r0);
    __stcs((float4*)(h1o + base1 + 256),  h1r1);
    __stcs((float4*)(v1o + base1),        v1r0);
    __stcs((float4*)(v1o + base1 + 256),  v1r1);
    __stcs((float4*)(d1o + base1),        d1r0);
    __stcs((float4*)(d1o + base1 + 256),  d1r1);

    // level-2: [96,128,128], row h, cols 2*w8, 2*w8+1 -> float2
    size_t base2 = (size_t)bc * 16384u + (size_t)h * 128u + 2u * w8;
    __stcs((float2*)(out + base2),                        a2v);
    __stcs((float2*)(out + (size_t)L2ELEMS     + base2),  h2v);
    __stcs((float2*)(out + (size_t)2 * L2ELEMS + base2),  v2v);
    __stcs((float2*)(out + (size_t)3 * L2ELEMS + base2),  d2v);
}

extern "C" void kernel_launch(void* const* d_in, const int* in_sizes, int n_in,
                              void* d_out, int out_size)
{
    const float* x = (const float*)d_in[0];
    float* out = (float*)d_out;
    // one thread per 4x8 input block: 96 * 128 * 64 threads
    unsigned total = 96u * 128u * 64u;
    haar2_kernel<<<total / 256u, 256u>>>(x, out);
}